// round 1
// baseline (speedup 1.0000x reference)
#include <cuda_runtime.h>
#include <cuda_bf16.h>
#include <math.h>

// HopAttentionLayer: B=256, T=64, N=2048, D=128
// scores[b,n] = tgt_term[b] + T*(ctx_term[b,n] + b0); softmax over n.
// tgt_term[b] and T*b0 are constant across n -> softmax shift invariance
// means attention[b,n] = softmax_n( T * <context[b,n,:], W[D:2D]> ).
// out[b,n,d] = attention[b,n] * context[b,n,d].
//
// One CTA (1024 threads) per batch. Phase A: warp-per-n dot (coalesced
// float4). Softmax in smem. Phase B: streaming scale, float4 coalesced.

#define BB 256
#define NN 2048
#define DD 128
#define TPB 1024
#define NWARP (TPB / 32)

__global__ __launch_bounds__(TPB, 2)
void hop_attention_kernel(const float* __restrict__ ctx,
                          const float* __restrict__ W,
                          float* __restrict__ out)
{
    const int b = blockIdx.x;
    const float* __restrict__ cb = ctx + (size_t)b * NN * DD;
    float* __restrict__ ob = out + (size_t)b * NN * DD;

    __shared__ float s[NN];        // scores -> exp values
    __shared__ float red[NWARP];   // cross-warp reduction scratch
    __shared__ float stat[2];      // [0]=max, [1]=sum

    const int tid  = threadIdx.x;
    const int lane = tid & 31;
    const int warp = tid >> 5;

    // Wc = W[128..255]; lane l owns 4 contiguous components.
    const float4 wc = reinterpret_cast<const float4*>(W + DD)[lane];

    // ---------------- Phase A: scores = 64 * <ctx[n,:], Wc> ----------------
    #pragma unroll 4
    for (int n = warp; n < NN; n += NWARP) {
        const float4 c = reinterpret_cast<const float4*>(cb + n * DD)[lane];
        float d = fmaf(c.x, wc.x, fmaf(c.y, wc.y, fmaf(c.z, wc.z, c.w * wc.w)));
        #pragma unroll
        for (int o = 16; o > 0; o >>= 1)
            d += __shfl_xor_sync(0xffffffffu, d, o);
        if (lane == 0) s[n] = d * 64.0f;   // T = 64
    }
    __syncthreads();

    // ---------------- Softmax over n (block reduction) ----------------
    // max
    float m = -INFINITY;
    #pragma unroll
    for (int i = tid; i < NN; i += TPB) m = fmaxf(m, s[i]);
    #pragma unroll
    for (int o = 16; o > 0; o >>= 1)
        m = fmaxf(m, __shfl_xor_sync(0xffffffffu, m, o));
    if (lane == 0) red[warp] = m;
    __syncthreads();
    if (warp == 0) {
        m = red[lane];
        #pragma unroll
        for (int o = 16; o > 0; o >>= 1)
            m = fmaxf(m, __shfl_xor_sync(0xffffffffu, m, o));
        if (lane == 0) stat[0] = m;
    }
    __syncthreads();
    m = stat[0];

    // exp + sum
    float sum = 0.0f;
    #pragma unroll
    for (int i = tid; i < NN; i += TPB) {
        float e = __expf(s[i] - m);
        s[i] = e;
        sum += e;
    }
    #pragma unroll
    for (int o = 16; o > 0; o >>= 1)
        sum += __shfl_xor_sync(0xffffffffu, sum, o);
    if (lane == 0) red[warp] = sum;
    __syncthreads();
    if (warp == 0) {
        sum = red[lane];
        #pragma unroll
        for (int o = 16; o > 0; o >>= 1)
            sum += __shfl_xor_sync(0xffffffffu, sum, o);
        if (lane == 0) stat[1] = sum;
    }
    __syncthreads();
    const float inv = 1.0f / stat[1];

    // ---------------- Phase B: out = attn[n] * ctx ----------------
    const float4* __restrict__ cb4 = reinterpret_cast<const float4*>(cb);
    float4* __restrict__ ob4 = reinterpret_cast<float4*>(ob);
    const int total4 = NN * DD / 4;   // 65536 float4, 32 per row
    #pragma unroll 4
    for (int i = tid; i < total4; i += TPB) {
        const float a = s[i >> 5] * inv;
        float4 c = cb4[i];
        c.x *= a; c.y *= a; c.z *= a; c.w *= a;
        ob4[i] = c;
    }
}

extern "C" void kernel_launch(void* const* d_in, const int* in_sizes, int n_in,
                              void* d_out, int out_size)
{
    // metadata order: targetsentence_emb, context_emb, W, b
    // targetsentence_emb and b are mathematically irrelevant (softmax shift
    // invariance) — never read.
    const float* ctx = (const float*)d_in[1];
    const float* W   = (const float*)d_in[2];
    float* out = (float*)d_out;

    hop_attention_kernel<<<BB, TPB>>>(ctx, W, out);
}